// round 5
// baseline (speedup 1.0000x reference)
#include <cuda_runtime.h>
#include <cuda_bf16.h>

// Shapes (fixed)
#define B_   4
#define N_   8192
#define M2_  8192
#define M3_  4096
#define M4_  2048
#define MM_  4096
#define C_   32
#define BN_  (B_ * N_)

#define TPB   256
#define SPLIT 8
#define QPT   4                       // queries per thread (packed 2x f32x2)
#define QPB   ((TPB / SPLIT) * QPT)   // 128 queries per block
#define TILE  2048                    // known points per smem tile

typedef unsigned long long ull;

// scratch (no allocations allowed)
__device__ float d_v[96];
__device__ float d_g[B_ * (M2_ + M3_ + M4_)];

// ---------------------------------------------------------------------------
// packed f32x2 helpers (lane-wise IEEE rn — bit-identical to scalar ops)
__device__ __forceinline__ ull f2pack(float lo, float hi) {
    ull r; asm("mov.b64 %0,{%1,%2};" : "=l"(r) : "f"(lo), "f"(hi)); return r;
}
__device__ __forceinline__ void f2unpack(float& lo, float& hi, ull v) {
    asm("mov.b64 {%0,%1},%2;" : "=f"(lo), "=f"(hi) : "l"(v));
}
__device__ __forceinline__ ull add2(ull a, ull b) {
    ull r; asm("add.rn.f32x2 %0,%1,%2;" : "=l"(r) : "l"(a), "l"(b)); return r;
}
__device__ __forceinline__ ull mul2(ull a, ull b) {
    ull r; asm("mul.rn.f32x2 %0,%1,%2;" : "=l"(r) : "l"(a), "l"(b)); return r;
}
__device__ __forceinline__ ull fma2(ull a, ull b, ull c) {
    ull r; asm("fma.rn.f32x2 %0,%1,%2,%3;" : "=l"(r) : "l"(a), "l"(b), "l"(c)); return r;
}

// reference-order squared norm: (x*x + y*y) + z*z, each op rounded once
__device__ __forceinline__ float norm2_ref(float x, float y, float z) {
    return __fadd_rn(__fadd_rn(__fmul_rn(x, x), __fmul_rn(y, y)), __fmul_rn(z, z));
}

// ---------------------------------------------------------------------------
// v[k] = sum_j w_cls[0,j] * w_fc[j,k]
__global__ void compute_v_kernel(const float* __restrict__ w_fc,
                                 const float* __restrict__ w_cls) {
    int k = threadIdx.x;
    if (k < 96) {
        float acc = 0.f;
#pragma unroll
        for (int j = 0; j < 64; ++j)
            acc += w_cls[j] * w_fc[j * 96 + k];
        d_v[k] = acc;
    }
}

// g[p] = feats[p,:] . v_seg — one warp per known point
__global__ void compute_g_kernel(const float* __restrict__ f2,
                                 const float* __restrict__ f3,
                                 const float* __restrict__ f4) {
    int warp = (blockIdx.x * blockDim.x + threadIdx.x) >> 5;
    int lane = threadIdx.x & 31;
    const int NG2 = B_ * M2_, NG3 = B_ * M3_, NG4 = B_ * M4_;
    const float* src;
    int base, voff, p = warp;
    if (p < NG2)                  { src = f2; base = 0;         voff = 0;  }
    else if (p < NG2 + NG3)       { p -= NG2; src = f3; base = NG2;        voff = 32; }
    else if (p < NG2 + NG3 + NG4) { p -= NG2 + NG3; src = f4; base = NG2 + NG3; voff = 64; }
    else return;
    float x = src[p * C_ + lane] * d_v[voff + lane];
#pragma unroll
    for (int o = 16; o; o >>= 1) x += __shfl_xor_sync(0xffffffffu, x, o);
    if (lane == 0) d_g[base + p] = x;
}

// ---------------------------------------------------------------------------
// insert into ascending top-3 (caller already checked d < d2).
// Strict '<' + ascending-index scan emulates top_k's lowest-index tie-break.
__device__ __forceinline__ void ins3(float d, float g, int idx,
                                     float& d0, float& d1, float& d2,
                                     float& g0, float& g1, float& g2,
                                     int& i0, int& i1, int& i2) {
    if (d < d1) {
        d2 = d1; g2 = g1; i2 = i1;
        if (d < d0) { d1 = d0; g1 = g0; i1 = i0; d0 = d; g0 = g; i0 = idx; }
        else        { d1 = d;  g1 = g;  i1 = idx; }
    } else { d2 = d; g2 = g; i2 = idx; }
}

__device__ __forceinline__ bool ltlex(float ad, int ai, float bd, int bi) {
    return (ad < bd) || (ad == bd && ai < bi);
}

// merge two ascending (d, idx)-lex-sorted triples, keep smallest 3
__device__ __forceinline__ void merge3lex(
    float& a0, float& a1, float& a2, float& g0, float& g1, float& g2,
    int& i0, int& i1, int& i2,
    float b0, float b1, float b2, float h0, float h1, float h2,
    int j0, int j1, int j2) {
    bool t = ltlex(a0, i0, b0, j0);
    float o0 = t ? a0 : b0; float og0 = t ? g0 : h0; int oi0 = t ? i0 : j0;
    float x0 = t ? a1 : b1; float xg0 = t ? g1 : h1; int xi0 = t ? i1 : j1;
    float x1 = t ? a2 : b2; float xg1 = t ? g2 : h2; int xi1 = t ? i2 : j2;
    float y0 = t ? b0 : a0; float yg0 = t ? h0 : g0; int yi0 = t ? j0 : i0;
    float y1 = t ? b1 : a1; float yg1 = t ? h1 : g1; int yi1 = t ? j1 : i1;
    bool u = ltlex(x0, xi0, y0, yi0);
    float o1 = u ? x0 : y0; float og1 = u ? xg0 : yg0; int oi1 = u ? xi0 : yi0;
    float z0 = u ? x1 : y1; float zg0 = u ? xg1 : yg1; int zi0 = u ? xi1 : yi1;
    float z1 = u ? y0 : x0; float zg1 = u ? yg0 : xg0; int zi1 = u ? yi0 : xi0;
    bool v = ltlex(z0, zi0, z1, zi1);
    a0 = o0; a1 = o1; a2 = v ? z0 : z1;
    g0 = og0; g1 = og1; g2 = v ? zg0 : zg1;
    i0 = oi0; i1 = oi1; i2 = v ? zi0 : zi1;
}

// ---------------------------------------------------------------------------
// One scale: exact-reference-rounding 3-NN over M points, weighted g-sum.
template <int M>
__device__ __forceinline__ void scale_nn(
    const float* __restrict__ coord, const float* __restrict__ gsrc,
    const ull* qx2, const ull* qy2, const ull* qz2, const ull* Sq2, ull NEG2,
    int tid, int split, float4* s_pt, float* s_g, float* pred) {
    const float INF = __int_as_float(0x7f800000);
    float D[QPT][3], G[QPT][3];
    int   I[QPT][3];
#pragma unroll
    for (int j = 0; j < QPT; ++j) {
        D[j][0] = D[j][1] = D[j][2] = INF;
        G[j][0] = G[j][1] = G[j][2] = 0.f;
        I[j][0] = I[j][1] = I[j][2] = 0x7fffffff;
    }

    for (int t0 = 0; t0 < M; t0 += TILE) {
        __syncthreads();
        for (int p = tid; p < TILE; p += TPB) {
            float x = coord[(t0 + p) * 3 + 0];
            float y = coord[(t0 + p) * 3 + 1];
            float z = coord[(t0 + p) * 3 + 2];
            s_pt[p] = make_float4(x, y, z, norm2_ref(x, y, z));
            s_g[p]  = gsrc[t0 + p];
        }
        __syncthreads();
#pragma unroll 4
        for (int i = 0; i < TILE / SPLIT; ++i) {
            int loc = (i << 3) | split;
            float4 c = s_pt[loc];
            ull kx2 = f2pack(c.x, c.x), ky2 = f2pack(c.y, c.y);
            ull kz2 = f2pack(c.z, c.z), kw2 = f2pack(c.w, c.w);
#pragma unroll
            for (int h = 0; h < 2; ++h) {
                // d2 = (Sq + Sk) - 2*(qx*kx + qy*ky + qz*kz), ref rounding
                ull t  = add2(Sq2[h], kw2);
                ull cr = mul2(qx2[h], kx2);
                cr = fma2(qy2[h], ky2, cr);
                cr = fma2(qz2[h], kz2, cr);
                ull dd = fma2(NEG2, cr, t);
                float da, db; f2unpack(da, db, dd);
                if (da < D[2 * h][2])
                    ins3(da, s_g[loc], t0 + loc,
                         D[2*h][0], D[2*h][1], D[2*h][2],
                         G[2*h][0], G[2*h][1], G[2*h][2],
                         I[2*h][0], I[2*h][1], I[2*h][2]);
                if (db < D[2 * h + 1][2])
                    ins3(db, s_g[loc], t0 + loc,
                         D[2*h+1][0], D[2*h+1][1], D[2*h+1][2],
                         G[2*h+1][0], G[2*h+1][1], G[2*h+1][2],
                         I[2*h+1][0], I[2*h+1][1], I[2*h+1][2]);
            }
        }
    }
    // merge 8 split lanes (lexicographic = top_k stable order), then weights
#pragma unroll
    for (int j = 0; j < QPT; ++j) {
        float d0 = D[j][0], d1 = D[j][1], d2 = D[j][2];
        float g0 = G[j][0], g1 = G[j][1], g2 = G[j][2];
        int   i0 = I[j][0], i1 = I[j][1], i2 = I[j][2];
#pragma unroll
        for (int off = 1; off < SPLIT; off <<= 1) {
            float b0 = __shfl_xor_sync(0xffffffffu, d0, off);
            float b1 = __shfl_xor_sync(0xffffffffu, d1, off);
            float b2 = __shfl_xor_sync(0xffffffffu, d2, off);
            float h0 = __shfl_xor_sync(0xffffffffu, g0, off);
            float h1 = __shfl_xor_sync(0xffffffffu, g1, off);
            float h2 = __shfl_xor_sync(0xffffffffu, g2, off);
            int   j0 = __shfl_xor_sync(0xffffffffu, i0, off);
            int   j1 = __shfl_xor_sync(0xffffffffu, i1, off);
            int   j2 = __shfl_xor_sync(0xffffffffu, i2, off);
            merge3lex(d0, d1, d2, g0, g1, g2, i0, i1, i2,
                      b0, b1, b2, h0, h1, h2, j0, j1, j2);
        }
        float c0 = fmaxf(d0, 0.f), c1 = fmaxf(d1, 0.f), c2 = fmaxf(d2, 0.f);
        float r0 = 1.f / (c0 + 1e-8f);
        float r1 = 1.f / (c1 + 1e-8f);
        float r2 = 1.f / (c2 + 1e-8f);
        float S  = __fadd_rn(__fadd_rn(r0, r1), r2);
        float w0 = r0 / S, w1 = r1 / S, w2 = r2 / S;
        pred[j] += __fadd_rn(__fadd_rn(__fmul_rn(w0, g0), __fmul_rn(w1, g1)),
                             __fmul_rn(w2, g2));
    }
}

// min d2 over match points (same reference rounding)
template <int M>
__device__ __forceinline__ void mask_min(
    const float* __restrict__ coord,
    const ull* qx2, const ull* qy2, const ull* qz2, const ull* Sq2, ull NEG2,
    int tid, int split, float4* s_pt, float* mind) {
    for (int t0 = 0; t0 < M; t0 += TILE) {
        __syncthreads();
        for (int p = tid; p < TILE; p += TPB) {
            float x = coord[(t0 + p) * 3 + 0];
            float y = coord[(t0 + p) * 3 + 1];
            float z = coord[(t0 + p) * 3 + 2];
            s_pt[p] = make_float4(x, y, z, norm2_ref(x, y, z));
        }
        __syncthreads();
#pragma unroll 4
        for (int i = 0; i < TILE / SPLIT; ++i) {
            int loc = (i << 3) | split;
            float4 c = s_pt[loc];
            ull kx2 = f2pack(c.x, c.x), ky2 = f2pack(c.y, c.y);
            ull kz2 = f2pack(c.z, c.z), kw2 = f2pack(c.w, c.w);
#pragma unroll
            for (int h = 0; h < 2; ++h) {
                ull t  = add2(Sq2[h], kw2);
                ull cr = mul2(qx2[h], kx2);
                cr = fma2(qy2[h], ky2, cr);
                cr = fma2(qz2[h], kz2, cr);
                ull dd = fma2(NEG2, cr, t);
                float da, db; f2unpack(da, db, dd);
                mind[2 * h]     = fminf(mind[2 * h], da);
                mind[2 * h + 1] = fminf(mind[2 * h + 1], db);
            }
        }
    }
#pragma unroll
    for (int j = 0; j < QPT; ++j)
#pragma unroll
        for (int off = 1; off < SPLIT; off <<= 1)
            mind[j] = fminf(mind[j], __shfl_xor_sync(0xffffffffu, mind[j], off));
}

// ---------------------------------------------------------------------------
__global__ __launch_bounds__(TPB)
void height_compression_main(const float* __restrict__ pts,
                             const float* __restrict__ k2,
                             const float* __restrict__ k3,
                             const float* __restrict__ k4,
                             const float* __restrict__ mp,
                             float* __restrict__ out) {
    __shared__ float4 s_pt[TILE];
    __shared__ float  s_g[TILE];

    const int tid = threadIdx.x;
    const int split = tid & (SPLIT - 1);
    const int qg = tid >> 3;
    const int q0 = blockIdx.x * QPB + qg * QPT;
    const int b = q0 >> 13;  // / N_

    float qx[QPT], qy[QPT], qz[QPT], Sq[QPT];
#pragma unroll
    for (int j = 0; j < QPT; ++j) {
        qx[j] = pts[(q0 + j) * 3 + 0];
        qy[j] = pts[(q0 + j) * 3 + 1];
        qz[j] = pts[(q0 + j) * 3 + 2];
        Sq[j] = norm2_ref(qx[j], qy[j], qz[j]);
    }
    ull qx2[2], qy2[2], qz2[2], Sq2[2];
#pragma unroll
    for (int h = 0; h < 2; ++h) {
        qx2[h] = f2pack(qx[2*h], qx[2*h+1]);
        qy2[h] = f2pack(qy[2*h], qy[2*h+1]);
        qz2[h] = f2pack(qz[2*h], qz[2*h+1]);
        Sq2[h] = f2pack(Sq[2*h], Sq[2*h+1]);
    }
    const ull NEG2 = f2pack(-2.f, -2.f);

    float pred[QPT] = {0.f, 0.f, 0.f, 0.f};
    scale_nn<M2_>(k2 + (size_t)b * M2_ * 3, d_g + (size_t)b * M2_,
                  qx2, qy2, qz2, Sq2, NEG2, tid, split, s_pt, s_g, pred);
    scale_nn<M3_>(k3 + (size_t)b * M3_ * 3, d_g + B_ * M2_ + (size_t)b * M3_,
                  qx2, qy2, qz2, Sq2, NEG2, tid, split, s_pt, s_g, pred);
    scale_nn<M4_>(k4 + (size_t)b * M4_ * 3,
                  d_g + B_ * (M2_ + M3_) + (size_t)b * M4_,
                  qx2, qy2, qz2, Sq2, NEG2, tid, split, s_pt, s_g, pred);

    float mind[QPT] = {__int_as_float(0x7f800000), __int_as_float(0x7f800000),
                       __int_as_float(0x7f800000), __int_as_float(0x7f800000)};
    mask_min<MM_>(mp + (size_t)b * MM_ * 3,
                  qx2, qy2, qz2, Sq2, NEG2, tid, split, s_pt, mind);

    if (split == 0) {
#pragma unroll
        for (int j = 0; j < QPT; ++j) {
            out[q0 + j] = pred[j];
            float md = sqrtf(fmaxf(mind[j], 0.f));   // ref: sqrt then < 0.5
            out[BN_ + q0 + j] = (md < 0.5f) ? 1.0f : 0.0f;
        }
    }
}

// ---------------------------------------------------------------------------
extern "C" void kernel_launch(void* const* d_in, const int* in_sizes, int n_in,
                              void* d_out, int out_size) {
    const float* pts  = (const float*)d_in[0];
    const float* k2   = (const float*)d_in[1];
    const float* f2   = (const float*)d_in[2];
    const float* k3   = (const float*)d_in[3];
    const float* f3   = (const float*)d_in[4];
    const float* k4   = (const float*)d_in[5];
    const float* f4   = (const float*)d_in[6];
    const float* mp   = (const float*)d_in[7];
    const float* wfc  = (const float*)d_in[8];
    const float* wcls = (const float*)d_in[9];

    compute_v_kernel<<<1, 96>>>(wfc, wcls);
    compute_g_kernel<<<(57344 * 32) / 256, 256>>>(f2, f3, f4);
    height_compression_main<<<BN_ / QPB, TPB>>>(pts, k2, k3, k4, mp,
                                                (float*)d_out);
}